// round 17
// baseline (speedup 1.0000x reference)
#include <cuda_runtime.h>
#include <cuda_bf16.h>
#include <cstdint>

// ----------------------------------------------------------------------------
// DPO loss on GB300 (sm_103 base target — legacy bf16 HMMA, rt=8 ceiling).
// Round 17: R16 champion + final_kernel fused into reduce_lz via threadfence
// reduction (last block computes the DPO scalar). Counter reset in convert
// (prior launch, stream-ordered) keeps graph replays deterministic.
// ----------------------------------------------------------------------------

#define BM 128
#define BN 128
#define KC 64                 // K elems per stage: 128B rows (SW128 swizzle)
#define NSTAGE 3
#define THREADS 128

static constexpr int Hdim   = 4096;
static constexpr int Mtot   = 4096;          // 8*512 tokens
static constexpr int Vdim   = 32000;
static constexpr int NT_PER = Vdim / BN;     // 250 N-tiles per matrix
static constexpr int NT_TOT = 2 * NT_PER;    // 500
static constexpr int NKT    = Hdim / KC;     // 64 k-chunks

static constexpr int A_BYTES  = BM * 128;    // 16 KB
static constexpr int B_BYTES  = BN * 128;    // 16 KB
static constexpr int STAGE_B  = A_BYTES + B_BYTES;          // 32 KB
static constexpr int DSMEM    = 1024 + NSTAGE * STAGE_B;    // ~97 KB

static constexpr int LZ_BLOCKS = Mtot / 32;  // 128

// ---------------- scratch (allocation-free __device__ globals) ----------------
__device__ __nv_bfloat16 g_xbf[(size_t)Mtot * Hdim];   //  33.5 MB
__device__ __nv_bfloat16 g_wbf[(size_t)Vdim * Hdim];   // 262 MB
__device__ __nv_bfloat16 g_rbf[(size_t)Vdim * Hdim];   // 262 MB
__device__ float g_pmax[NT_TOT * Mtot];
__device__ float g_psum[NT_TOT * Mtot];
__device__ float g_tokW[Mtot];
__device__ float g_tokR[Mtot];
__device__ float g_lzW[Mtot];
__device__ float g_lzR[Mtot];
__device__ unsigned int g_done;              // reset by convert kernel each run

__device__ __forceinline__ uint32_t smem_u32(const void* p) {
    return (uint32_t)__cvta_generic_to_shared(p);
}
__device__ __forceinline__ void cp_async16(uint32_t dst, const void* src) {
    asm volatile("cp.async.cg.shared.global [%0], [%1], 16;\n" :: "r"(dst), "l"(src));
}
#define SWZ(x) ((x) ^ (((x) >> 3) & 0x70))

// Inline y-dtype detection (serial form, off the critical path in tok blocks).
__device__ __forceinline__ int y_is64(const void* y) {
    const int* y32 = (const int*)y;
    int is64 = 1;
#pragma unroll 8
    for (int i = 0; i < 64; i++) {
        int hi = y32[2 * i + 1];
        if (hi != 0 && hi != -1) { is64 = 0; break; }
    }
    return is64;
}
__device__ __forceinline__ int get_label(const void* y, int m, int is64) {
    if (is64) return (int)((const long long*)y)[m];
    return ((const int*)y)[m];
}

// ----------------------------------------------------------------------------
// Fused: fp32 -> bf16 convert (blocks 0..4095) + exact token logits (blocks
// 4096..4607). Block 0 also resets the completion counter (stream-ordered
// before reduce_lz, so every graph replay starts from zero).
// ----------------------------------------------------------------------------
static constexpr size_t N8_X = (size_t)Mtot * Hdim / 8;
static constexpr size_t N8_W = (size_t)Vdim * Hdim / 8;
static constexpr size_t N8_TOT = N8_X + 2 * N8_W;
static constexpr int CONV_BLOCKS = 4096;
static constexpr int TOK_BLOCKS  = Mtot / 8;   // 512

__global__ __launch_bounds__(256) void convert_tok_kernel(
    const float* __restrict__ x, const float* __restrict__ W,
    const float* __restrict__ R, const void* __restrict__ y)
{
    if (blockIdx.x == 0 && threadIdx.x == 0) g_done = 0u;
    if (blockIdx.x < CONV_BLOCKS) {
        size_t i = (size_t)blockIdx.x * blockDim.x + threadIdx.x;
        const size_t stride = (size_t)CONV_BLOCKS * blockDim.x;
        for (; i < N8_TOT; i += stride) {
            const float* src;
            __nv_bfloat16* dst;
            size_t j;
            if (i < N8_X)               { src = x; dst = g_xbf; j = i; }
            else if (i < N8_X + N8_W)   { src = W; dst = g_wbf; j = i - N8_X; }
            else                        { src = R; dst = g_rbf; j = i - N8_X - N8_W; }
            const float4* s = reinterpret_cast<const float4*>(src) + 2 * j;
            float4 a = s[0], b = s[1];
            __nv_bfloat162 o[4] = {
                __floats2bfloat162_rn(a.x, a.y), __floats2bfloat162_rn(a.z, a.w),
                __floats2bfloat162_rn(b.x, b.y), __floats2bfloat162_rn(b.z, b.w)};
            *reinterpret_cast<uint4*>(dst + j * 8) = *reinterpret_cast<const uint4*>(o);
        }
    } else {
        // token-logit blocks: one warp per token, fp32 exact
        const int blk  = blockIdx.x - CONV_BLOCKS;      // 0..511
        const int warp = threadIdx.x >> 5, lane = threadIdx.x & 31;
        const int m = blk * 8 + warp;
        const int is64 = y_is64(y);
        int idx = get_label(y, m, is64);
        if (idx < 0 || idx >= Vdim) idx = 0;            // defensive clamp
        const float4* xr = reinterpret_cast<const float4*>(x + (size_t)m   * Hdim);
        const float4* wr = reinterpret_cast<const float4*>(W + (size_t)idx * Hdim);
        const float4* rr = reinterpret_cast<const float4*>(R + (size_t)idx * Hdim);
        float sw = 0.f, sr = 0.f;
        for (int j = lane; j < Hdim / 4; j += 32) {
            float4 a = xr[j], b = wr[j], c = rr[j];
            sw += a.x * b.x + a.y * b.y + a.z * b.z + a.w * b.w;
            sr += a.x * c.x + a.y * c.y + a.z * c.z + a.w * c.w;
        }
#pragma unroll
        for (int o = 16; o > 0; o >>= 1) {
            sw += __shfl_xor_sync(0xffffffffu, sw, o);
            sr += __shfl_xor_sync(0xffffffffu, sr, o);
        }
        if (lane == 0) { g_tokW[m] = sw; g_tokR[m] = sr; }
    }
}

// ----------------------------------------------------------------------------
// Main GEMM + online LSE epilogue. grid=(32 mt [fast], 500 nt), block=128.
// 4 warps in a 2x2 (M x N) grid; each warp computes 64x64. (champion mainloop)
// ----------------------------------------------------------------------------
__global__ __launch_bounds__(THREADS, 2) void lse_kernel()
{
    extern __shared__ char dsm[];
    const uint32_t raw  = smem_u32(dsm);
    const uint32_t stg  = (raw + 1023) & ~1023u;   // 1024-aligned

    __shared__ float s_red[BM * 2];
    __shared__ float s_rowmax[BM];

    const int tid  = threadIdx.x;
    const int warp = tid >> 5, lane = tid & 31;
    const int wm   = warp >> 1, wn = warp & 1;     // 2 x 2 warp grid

    const int mt = blockIdx.x, nt = blockIdx.y;
    const int m0 = mt * BM;
    const int n0 = (nt < NT_PER ? nt : nt - NT_PER) * BN;
    const __nv_bfloat16* asrc = g_xbf + (size_t)m0 * Hdim;
    const __nv_bfloat16* bsrc = ((nt < NT_PER) ? g_wbf : g_rbf) + (size_t)n0 * Hdim;

    float acc[4][8][4];            // 128 fp32 accumulators / thread
#pragma unroll
    for (int i = 0; i < 4; i++)
#pragma unroll
        for (int j = 0; j < 8; j++)
#pragma unroll
            for (int c = 0; c < 4; c++) acc[i][j][c] = 0.f;

    auto load_stage = [&](int slot, int kt) {
        const uint32_t a_base = stg + slot * STAGE_B;
        const uint32_t b_base = a_base + A_BYTES;
        const int k0 = kt * KC;
#pragma unroll
        for (int i = 0; i < 8; i++) {
            int id  = tid + i * THREADS;      // 0..1023
            int row = id >> 3, c = id & 7;    // 128 rows x 8 chunks
            cp_async16(a_base + SWZ(row * 128 + c * 16),
                       asrc + (size_t)row * Hdim + k0 + c * 8);
            cp_async16(b_base + SWZ(row * 128 + c * 16),
                       bsrc + (size_t)row * Hdim + k0 + c * 8);
        }
        asm volatile("cp.async.commit_group;" ::: "memory");
    };

    auto compute = [&](int slot) {
        const uint32_t a_base = stg + slot * STAGE_B;
        const uint32_t b_base = a_base + A_BYTES;
#pragma unroll
        for (int ks = 0; ks < 4; ks++) {       // 4 x K=16 inside the 64 chunk
            uint32_t af[4][4], bf[8][2];
            const int arow = wm * 64 + (lane & 15);
            const int asel = (lane >> 4) & 1;
#pragma unroll
            for (int mi = 0; mi < 4; mi++) {
                uint32_t addr = a_base +
                    SWZ((uint32_t)(arow + mi * 16) * 128 + ks * 32 + asel * 16);
                asm volatile("ldmatrix.sync.aligned.m8n8.x4.shared.b16 {%0,%1,%2,%3}, [%4];"
                             : "=r"(af[mi][0]), "=r"(af[mi][1]),
                               "=r"(af[mi][2]), "=r"(af[mi][3])
                             : "r"(addr));
            }
            // B: x4 over pairs of 8-col groups.
#pragma unroll
            for (int np = 0; np < 4; np++) {
                const uint32_t brow = wn * 64 + np * 16 +
                                      ((lane >> 4) << 3) + (lane & 7);
                const uint32_t bsel = (lane >> 3) & 1;
                uint32_t addr = b_base + SWZ(brow * 128 + ks * 32 + bsel * 16);
                asm volatile("ldmatrix.sync.aligned.m8n8.x4.shared.b16 {%0,%1,%2,%3}, [%4];"
                             : "=r"(bf[2 * np][0]), "=r"(bf[2 * np][1]),
                               "=r"(bf[2 * np + 1][0]), "=r"(bf[2 * np + 1][1])
                             : "r"(addr));
            }
#pragma unroll
            for (int mi = 0; mi < 4; mi++)
#pragma unroll
                for (int ni = 0; ni < 8; ni++)
                    asm volatile(
                        "mma.sync.aligned.m16n8k16.row.col.f32.bf16.bf16.f32 "
                        "{%0,%1,%2,%3}, {%4,%5,%6,%7}, {%8,%9}, {%0,%1,%2,%3};"
                        : "+f"(acc[mi][ni][0]), "+f"(acc[mi][ni][1]),
                          "+f"(acc[mi][ni][2]), "+f"(acc[mi][ni][3])
                        : "r"(af[mi][0]), "r"(af[mi][1]), "r"(af[mi][2]), "r"(af[mi][3]),
                          "r"(bf[ni][0]), "r"(bf[ni][1]));
        }
    };

    // prologue: fill NSTAGE-1 stages
    load_stage(0, 0);
    load_stage(1, 1);

    for (int kt = 0; kt < NKT; kt++) {
        const int slot = kt % NSTAGE;
        if (kt + 2 < NKT) {
            asm volatile("cp.async.wait_group 1;" ::: "memory");
        } else {
            asm volatile("cp.async.wait_group 0;" ::: "memory");
        }
        __syncthreads();
        if (kt + 2 < NKT) load_stage((kt + 2) % NSTAGE, kt + 2);
        compute(slot);
    }

    // ---- fused epilogue: per-token max / sumexp over this 128-col tile ----
    const float NEG = -1e30f;
#pragma unroll
    for (int mi = 0; mi < 4; mi++) {
        float mlo = NEG, mhi = NEG;
#pragma unroll
        for (int ni = 0; ni < 8; ni++) {
            mlo = fmaxf(mlo, fmaxf(acc[mi][ni][0], acc[mi][ni][1]));
            mhi = fmaxf(mhi, fmaxf(acc[mi][ni][2], acc[mi][ni][3]));
        }
#pragma unroll
        for (int o = 1; o < 4; o <<= 1) {
            mlo = fmaxf(mlo, __shfl_xor_sync(0xffffffffu, mlo, o));
            mhi = fmaxf(mhi, __shfl_xor_sync(0xffffffffu, mhi, o));
        }
        if ((lane & 3) == 0) {
            int rlo = wm * 64 + mi * 16 + (lane >> 2);
            s_red[rlo * 2 + wn]       = mlo;
            s_red[(rlo + 8) * 2 + wn] = mhi;
        }
    }
    __syncthreads();
    if (tid < BM) {
        s_rowmax[tid] = fmaxf(s_red[tid * 2 + 0], s_red[tid * 2 + 1]);
    }
    __syncthreads();
#pragma unroll
    for (int mi = 0; mi < 4; mi++) {
        int rlo = wm * 64 + mi * 16 + (lane >> 2);
        int rhi = rlo + 8;
        float Mlo = s_rowmax[rlo], Mhi = s_rowmax[rhi];
        float slo = 0.f, shi = 0.f;
#pragma unroll
        for (int ni = 0; ni < 8; ni++) {
            slo += __expf(acc[mi][ni][0] - Mlo) + __expf(acc[mi][ni][1] - Mlo);
            shi += __expf(acc[mi][ni][2] - Mhi) + __expf(acc[mi][ni][3] - Mhi);
        }
#pragma unroll
        for (int o = 1; o < 4; o <<= 1) {
            slo += __shfl_xor_sync(0xffffffffu, slo, o);
            shi += __shfl_xor_sync(0xffffffffu, shi, o);
        }
        if ((lane & 3) == 0) {
            s_red[rlo * 2 + wn] = slo;
            s_red[rhi * 2 + wn] = shi;
        }
    }
    __syncthreads();
    if (tid < BM) {
        float s = s_red[tid * 2 + 0] + s_red[tid * 2 + 1];
        g_pmax[(size_t)nt * Mtot + m0 + tid] = s_rowmax[tid];
        g_psum[(size_t)nt * Mtot + m0 + tid] = s;
    }
}

// ----------------------------------------------------------------------------
// Fused logZ combine + DPO scalar. grid=128, block=1024.
// Phase 1 (all blocks): coalesced online-LSE merge -> g_lzW/g_lzR.
// Phase 2 (last block via threadfence reduction): per-sequence averages and
// the final loss. 32 warps <-> 8 batches x 4 quarter-warps, 4 tokens/thread.
// ----------------------------------------------------------------------------
__global__ __launch_bounds__(1024) void reduce_final_kernel(
    const void* __restrict__ y, float* __restrict__ out)
{
    __shared__ float s_mx[32][32];
    __shared__ float s_sv[32][32];
    const int tid = threadIdx.x;
    const int tg  = tid >> 5;            // nt-slice 0..31
    const int ml  = tid & 31;            // token within group
    const int m   = blockIdx.x * 32 + ml;

#pragma unroll
    for (int mat = 0; mat < 2; mat++) {
        const int base = mat * NT_PER;
        float mx = -1e30f, sv = 0.f;
        for (int nt = tg; nt < NT_PER; nt += 32) {
            const float p  = g_pmax[(size_t)(base + nt) * Mtot + m];
            const float ps = g_psum[(size_t)(base + nt) * Mtot + m];
            const float nm = fmaxf(mx, p);
            sv = sv * __expf(mx - nm) + ps * __expf(p - nm);
            mx = nm;
        }
        s_mx[tg][ml] = mx;
        s_sv[tg][ml] = sv;
        __syncthreads();
        if (tid < 32) {
            float M = -1e30f, S = 0.f;
#pragma unroll
            for (int g = 0; g < 32; g++) {
                const float p = s_mx[g][tid], ps = s_sv[g][tid];
                const float nm = fmaxf(M, p);
                S = S * __expf(M - nm) + ps * __expf(p - nm);
                M = nm;
            }
            const float lz = M + logf(S);
            if (mat == 0) g_lzW[m] = lz; else g_lzR[m] = lz;
        }
        __syncthreads();
    }

    // ---- threadfence reduction: last block computes the DPO scalar ----
    __shared__ bool s_last;
    __threadfence();                     // publish this block's lz writes
    if (tid == 0) {
        unsigned int prev = atomicAdd(&g_done, 1u);
        s_last = (prev == (unsigned int)(LZ_BLOCKS - 1));
    }
    __syncthreads();
    if (!s_last) return;

    // last block: all other blocks' lz writes are visible (fence+atomic order)
    __shared__ float s_p[32], s_r[32], s_c[32];
    __shared__ int   s_is64;
    const int warp = tid >> 5, lane = tid & 31;

    if (warp == 0) {                     // ballot dtype detect (64 slots)
        const int* y32 = (const int*)y;
        int hi0 = y32[2 * lane + 1];
        int hi1 = y32[2 * (lane + 32) + 1];
        bool ok = (hi0 == 0 || hi0 == -1) && (hi1 == 0 || hi1 == -1);
        uint32_t vote = __ballot_sync(0xffffffffu, ok);
        if (lane == 0) s_is64 = (vote == 0xffffffffu);
    }
    __syncthreads();
    const int is64 = s_is64;

    const int b = warp >> 2, q = warp & 3;   // batch 0..7, quarter 0..3
    float p = 0.f, r = 0.f, c = 0.f;
#pragma unroll
    for (int i = 0; i < 4; i++) {
        const int mm = b * 512 + q * 128 + i * 32 + lane;
        const int yv = get_label(y, mm, is64);
        if (yv != -100) {
            p += g_tokW[mm] - g_lzW[mm];
            r += g_tokR[mm] - g_lzR[mm];
            c += 1.f;
        }
    }
#pragma unroll
    for (int o = 16; o > 0; o >>= 1) {
        p += __shfl_xor_sync(0xffffffffu, p, o);
        r += __shfl_xor_sync(0xffffffffu, r, o);
        c += __shfl_xor_sync(0xffffffffu, c, o);
    }
    if (lane == 0) { s_p[warp] = p; s_r[warp] = r; s_c[warp] = c; }
    __syncthreads();

    if (tid == 0) {
        float pav[8], rav[8];
#pragma unroll
        for (int bb = 0; bb < 8; bb++) {
            float ps = 0.f, rs = 0.f, cs = 0.f;
#pragma unroll
            for (int qq = 0; qq < 4; qq++) {
                ps += s_p[4 * bb + qq];
                rs += s_r[4 * bb + qq];
                cs += s_c[4 * bb + qq];
            }
            pav[bb] = ps / cs;
            rav[bb] = rs / cs;
        }
        float loss = 0.f;
#pragma unroll
        for (int i = 0; i < 4; i++) {
            float z = 0.1f * ((pav[i] - rav[i]) - (pav[i + 4] - rav[i + 4]));
            loss += log1pf(expf(-z));
        }
        out[0] = loss * 0.25f;
    }
}

// ----------------------------------------------------------------------------
extern "C" void kernel_launch(void* const* d_in, const int* in_sizes, int n_in,
                              void* d_out, int out_size)
{
    const float* x = nullptr;
    const void*  y = nullptr;
    const float* Wm[2] = {nullptr, nullptr};
    int wcount = 0;
    for (int i = 0; i < n_in; i++) {
        if (in_sizes[i] == 16777216)                          x = (const float*)d_in[i];
        else if (in_sizes[i] == 4096 || in_sizes[i] == 8192)  y = d_in[i];
        else if (wcount < 2)                                  Wm[wcount++] = (const float*)d_in[i];
    }
    if (!x)      x     = (const float*)d_in[0];
    if (!y)      y     = d_in[1];
    if (!Wm[0])  Wm[0] = (const float*)d_in[2];
    if (!Wm[1])  Wm[1] = (const float*)d_in[3];
    const float* W    = Wm[0];
    const float* refW = Wm[1];

    cudaFuncSetAttribute(lse_kernel, cudaFuncAttributeMaxDynamicSharedMemorySize, DSMEM);

    convert_tok_kernel<<<CONV_BLOCKS + TOK_BLOCKS, 256>>>(x, W, refW, y);

    dim3 grid(Mtot / BM, NT_TOT);   // (32 [fast: x L2-resident], 500)
    lse_kernel<<<grid, THREADS, DSMEM>>>();

    reduce_final_kernel<<<LZ_BLOCKS, 1024>>>(y, (float*)d_out);
}